// round 8
// baseline (speedup 1.0000x reference)
#include <cuda_runtime.h>
#include <cstdint>

// GINENet: 2x GINEConv(F=128) + classifier(40) + log_softmax
// N=100000, E=1600000, F=128.
//
// R8 == R7 resubmit (R7 bench died to the recurring container infra failure,
// same as R0/R2; code audited, unchanged):
// edge-parallel streaming aggregation. Warps stream contiguous 128-edge
// chunks of the dst-sorted edge list with a depth-4 prefetch pipeline,
// segment-reduce in registers, store interior segments / atomicAdd chunk
// boundaries. Zero/base pre-pass per conv. MLP fusion + tf32 mma from R6.

#define NODES_MAX 100000
#define EDGE_MAX  1600000
#define FDIM 128

#define APAD 20
#define WPAD 136
#define TPAD 132
#define ECHUNK 128

__device__ float g_A[(size_t)NODES_MAX * FDIM];
__device__ float g_B[(size_t)NODES_MAX * FDIM];
__device__ int   g_rowptr[NODES_MAX + 1];
__device__ int   g_cur[NODES_MAX];
__device__ int   g_bsum[128];
__device__ int   g_srcS[EDGE_MAX];
__device__ int   g_dstS[EDGE_MAX];
__device__ float g_eaS[EDGE_MAX];
__device__ int   g_is64;

__device__ __forceinline__ float* bufsel(int s) { return (s == 0) ? g_A : g_B; }

__device__ __forceinline__ uint32_t f2tf32(float f) {
    uint32_t r;
    asm("cvt.rna.tf32.f32 %0, %1;" : "=r"(r) : "f"(f));
    return r;
}

__device__ __forceinline__ void mma_tf32(float* c, uint32_t a0, uint32_t a1,
                                         uint32_t a2, uint32_t a3,
                                         uint32_t b0, uint32_t b1) {
    asm volatile(
        "mma.sync.aligned.m16n8k8.row.col.f32.tf32.tf32.f32 "
        "{%0,%1,%2,%3}, {%4,%5,%6,%7}, {%8,%9}, {%0,%1,%2,%3};"
        : "+f"(c[0]), "+f"(c[1]), "+f"(c[2]), "+f"(c[3])
        : "r"(a0), "r"(a1), "r"(a2), "r"(a3), "r"(b0), "r"(b1));
}

// ---------------------------------------------------------------------------
// Detect int64 vs int32 edge_index.
// ---------------------------------------------------------------------------
__global__ void k_detect(const long long* __restrict__ ei, int n_nodes) {
    if (threadIdx.x == 0 && blockIdx.x == 0) {
        int ok = 1;
        for (int i = 0; i < 64; ++i) {
            long long v = ei[i];
            if (v < 0 || v >= (long long)n_nodes) { ok = 0; break; }
        }
        g_is64 = ok;
    }
}

__device__ __forceinline__ long long load_idx(const void* ei, long long off) {
    if (g_is64) return __ldg((const long long*)ei + off);
    return (long long)__ldg((const int*)ei + off);
}

// ---------------------------------------------------------------------------
// CSR build
// ---------------------------------------------------------------------------
__global__ void k_zero(int n) {
    int i = blockIdx.x * blockDim.x + threadIdx.x;
    if (i < n) g_cur[i] = 0;
}

__global__ void k_hist(const void* __restrict__ ei, int E) {
    int e = blockIdx.x * blockDim.x + threadIdx.x;
    if (e >= E) return;
    int dst = (int)load_idx(ei, (long long)E + e);
    atomicAdd(&g_cur[dst], 1);
}

__global__ void k_scan1(int n) {
    const int tid = threadIdx.x, lane = tid & 31, warp = tid >> 5;
    const int idx = blockIdx.x * 1024 + tid;
    int v = (idx < n) ? g_cur[idx] : 0;
    int inc = v;
#pragma unroll
    for (int o = 1; o < 32; o <<= 1) {
        int t = __shfl_up_sync(0xFFFFFFFFu, inc, o);
        if (lane >= o) inc += t;
    }
    __shared__ int ws[32];
    if (lane == 31) ws[warp] = inc;
    __syncthreads();
    if (warp == 0) {
        int wv = ws[lane];
        int winc = wv;
#pragma unroll
        for (int o = 1; o < 32; o <<= 1) {
            int t = __shfl_up_sync(0xFFFFFFFFu, winc, o);
            if (lane >= o) winc += t;
        }
        ws[lane] = winc - wv;
    }
    __syncthreads();
    int excl = inc - v + ws[warp];
    if (idx <= n) g_rowptr[idx] = excl;
    if (tid == 1023) g_bsum[blockIdx.x] = excl + v;
}

__global__ void k_scan2(int nb) {
    __shared__ int s[128];
    int t = threadIdx.x;
    s[t] = (t < nb) ? g_bsum[t] : 0;
    __syncthreads();
    if (t == 0) {
        int run = 0;
        for (int i = 0; i < nb; ++i) { int v = s[i]; s[i] = run; run += v; }
    }
    __syncthreads();
    g_bsum[t] = s[t];
}

__global__ void k_scan3(int n, int E) {
    int idx = blockIdx.x * blockDim.x + threadIdx.x;
    if (idx < n) {
        int r = g_rowptr[idx] + g_bsum[idx >> 10];
        g_rowptr[idx] = r;
        g_cur[idx] = r;
    }
    if (idx == 0) g_rowptr[n] = E;
}

__global__ void k_scatter(const void* __restrict__ ei, const float* __restrict__ ea,
                          int E) {
    int e = blockIdx.x * blockDim.x + threadIdx.x;
    if (e >= E) return;
    int src = (int)load_idx(ei, e);
    int dst = (int)load_idx(ei, (long long)E + e);
    int pos = atomicAdd(&g_cur[dst], 1);
    g_srcS[pos] = src;
    g_dstS[pos] = dst;
    g_eaS[pos] = __ldg(ea + e);
}

// ---------------------------------------------------------------------------
// h pre-pass: h[v] = 0 (deg>0) or (1+eps)*x[v] (deg==0). One warp per node.
// ---------------------------------------------------------------------------
__global__ __launch_bounds__(256) void k_zero_h(
    const float4* __restrict__ x_ext, int x_sel, int out_sel,
    const float* __restrict__ eps, int N) {
    const int warp = threadIdx.x >> 5, lane = threadIdx.x & 31;
    const int v = blockIdx.x * 8 + warp;
    if (v >= N) return;
    float4* h4 = (float4*)bufsel(out_sel);
    float4 z = make_float4(0.f, 0.f, 0.f, 0.f);
    if (__ldg(g_rowptr + v) == __ldg(g_rowptr + v + 1)) {
        const float4* x4 = x_ext ? x_ext : (const float4*)bufsel(x_sel);
        const float s = 1.0f + __ldg(eps);
        float4 xv = __ldg(x4 + (long long)v * 32 + lane);
        z.x = s * xv.x; z.y = s * xv.y; z.z = s * xv.z; z.w = s * xv.w;
    }
    h4[(long long)v * 32 + lane] = z;
}

// ---------------------------------------------------------------------------
// Edge-parallel aggregation: one warp per ECHUNK contiguous (dst-sorted)
// edges, depth-4 prefetch, register segment-reduce.
//   h[dst] (+)= relu(x[src] + a*We + be); base (1+eps)*x[dst] added by the
//   warp owning the segment start. Interior segment -> store, boundary ->
//   atomicAdd (h pre-zeroed by k_zero_h).
// ---------------------------------------------------------------------------
__global__ __launch_bounds__(256) void k_aggr_edge(
    const float4* __restrict__ x_ext, int x_sel, int out_sel,
    const float* __restrict__ eps,
    const float4* __restrict__ We4, const float4* __restrict__ be4, int E) {
    const int warp = threadIdx.x >> 5, lane = threadIdx.x & 31;
    const int ws = (blockIdx.x * 8 + warp) * ECHUNK;
    if (ws >= E) return;
    const int we = min(ws + ECHUNK, E);

    const float4* x4 = x_ext ? x_ext : (const float4*)bufsel(x_sel);
    float4* h4 = (float4*)bufsel(out_sel);

    const float s = 1.0f + __ldg(eps);
    const float4 w = __ldg(We4 + lane);
    const float4 b = __ldg(be4 + lane);

    const int P = 4;
    float pa[P]; int pdst[P]; float4 pxv[P];
#pragma unroll
    for (int i = 0; i < P; ++i) {
        const int e = ws + i;
        if (e < we) {
            const int sn = __ldg(g_srcS + e);
            pa[i] = __ldg(g_eaS + e);
            pdst[i] = __ldg(g_dstS + e);
            pxv[i] = __ldg(x4 + (long long)sn * 32 + lane);
        }
    }

    int cur = pdst[0];
    float4 acc = make_float4(0.f, 0.f, 0.f, 0.f);

    auto flush = [&](int v, float4 a4) {
        const int r0 = __ldg(g_rowptr + v);
        const int r1 = __ldg(g_rowptr + v + 1);
        const bool first = (r0 >= ws);
        const bool last = (r1 <= we);
        if (first) {  // segment starts here: add (1+eps)*x[v]
            float4 bv = __ldg(x4 + (long long)v * 32 + lane);
            a4.x = fmaf(s, bv.x, a4.x);
            a4.y = fmaf(s, bv.y, a4.y);
            a4.z = fmaf(s, bv.z, a4.z);
            a4.w = fmaf(s, bv.w, a4.w);
        }
        const long long off = (long long)v * 32 + lane;
        if (first && last) h4[off] = a4;
        else atomicAdd(h4 + off, a4);
    };

#pragma unroll 1
    for (int e = ws; e < we; ++e) {
        const int slot = (e - ws) & (P - 1);
        const int d = pdst[slot];
        const float a = pa[slot];
        const float4 xv = pxv[slot];
        const int en = e + P;
        if (en < we) {
            const int sn = __ldg(g_srcS + en);
            pa[slot] = __ldg(g_eaS + en);
            pdst[slot] = __ldg(g_dstS + en);
            pxv[slot] = __ldg(x4 + (long long)sn * 32 + lane);
        }
        if (d != cur) {
            flush(cur, acc);
            acc = make_float4(0.f, 0.f, 0.f, 0.f);
            cur = d;
        }
        acc.x += fmaxf(fmaf(a, w.x, b.x) + xv.x, 0.0f);
        acc.y += fmaxf(fmaf(a, w.y, b.y) + xv.y, 0.0f);
        acc.z += fmaxf(fmaf(a, w.z, b.z) + xv.z, 0.0f);
        acc.w += fmaxf(fmaf(a, w.w, b.w) + xv.w, 0.0f);
    }
    flush(cur, acc);
}

// ---------------------------------------------------------------------------
// Fused MLP: C = relu( relu(A@W1 + b1) @ W2 + b2 )  (tf32 mma, unchanged R6)
// ---------------------------------------------------------------------------
__global__ __launch_bounds__(256, 2) void k_mlp(
    int a_sel, const float* __restrict__ W1, const float* __restrict__ b1,
    const float* __restrict__ W2, const float* __restrict__ b2,
    int c_sel, int M) {
    const float* A = bufsel(a_sel);
    float* C = bufsel(c_sel);

    extern __shared__ float smem[];
    float* As = smem;
    float* Ws = As + 2 * 128 * APAD;
    float* Ts = Ws + 2 * 16 * WPAD;

    const int tid = threadIdx.x;
    const int lane = tid & 31;
    const int wid = tid >> 5;
    const int warp_m = wid & 1;
    const int warp_n = wid >> 1;
    const int rowBase = blockIdx.x * 128;

    const int g = lane >> 2;
    const int c = lane & 3;

    float acc[4][4][4];
#pragma unroll
    for (int i = 0; i < 4; ++i)
#pragma unroll
        for (int j = 0; j < 4; ++j)
#pragma unroll
            for (int q = 0; q < 4; ++q) acc[i][j][q] = 0.0f;

    const int a_row0 = tid >> 2;
    const int a_c4 = (tid & 3) << 2;
    const int w_k0 = tid >> 5;
    const int w_c4 = (tid & 31) << 2;

    // ================= GEMM 1: T = relu(A @ W1 + b1) =================
    {
#pragma unroll
        for (int it = 0; it < 2; ++it) {
            int row = a_row0 + it * 64;
            int grow = rowBase + row;
            float4 v = make_float4(0.f, 0.f, 0.f, 0.f);
            if (grow < M) v = __ldg((const float4*)(A + (long long)grow * 128 + a_c4));
            float* d = &As[row * APAD + a_c4];
            d[0] = __uint_as_float(f2tf32(v.x));
            d[1] = __uint_as_float(f2tf32(v.y));
            d[2] = __uint_as_float(f2tf32(v.z));
            d[3] = __uint_as_float(f2tf32(v.w));
            int k = w_k0 + it * 8;
            float4 wv = __ldg((const float4*)(W1 + k * 128 + w_c4));
            float* e = &Ws[k * WPAD + w_c4];
            e[0] = __uint_as_float(f2tf32(wv.x));
            e[1] = __uint_as_float(f2tf32(wv.y));
            e[2] = __uint_as_float(f2tf32(wv.z));
            e[3] = __uint_as_float(f2tf32(wv.w));
        }
    }
    __syncthreads();

#pragma unroll 1
    for (int kc = 0; kc < 8; ++kc) {
        const int cur = kc & 1;
        float4 pa[2], pw[2];
        if (kc < 7) {
#pragma unroll
            for (int it = 0; it < 2; ++it) {
                int row = a_row0 + it * 64;
                int grow = rowBase + row;
                pa[it] = make_float4(0.f, 0.f, 0.f, 0.f);
                if (grow < M)
                    pa[it] = __ldg((const float4*)(A + (long long)grow * 128 +
                                                   (kc + 1) * 16 + a_c4));
                int k = w_k0 + it * 8;
                pw[it] = __ldg((const float4*)(W1 + ((kc + 1) * 16 + k) * 128 + w_c4));
            }
        }
#pragma unroll
        for (int ks = 0; ks < 2; ++ks) {
            const int k = ks * 8;
            uint32_t aF[4][4], bF[4][2];
#pragma unroll
            for (int mt = 0; mt < 4; ++mt) {
                const int m = warp_m * 64 + mt * 16 + g;
                const float* p0 = &As[(cur * 128 + m) * APAD + k + c];
                const float* p1 = &As[(cur * 128 + m + 8) * APAD + k + c];
                aF[mt][0] = __float_as_uint(p0[0]);
                aF[mt][1] = __float_as_uint(p1[0]);
                aF[mt][2] = __float_as_uint(p0[4]);
                aF[mt][3] = __float_as_uint(p1[4]);
            }
#pragma unroll
            for (int nt = 0; nt < 4; ++nt) {
                const int n = warp_n * 32 + nt * 8 + g;
                bF[nt][0] = __float_as_uint(Ws[(cur * 16 + k + c) * WPAD + n]);
                bF[nt][1] = __float_as_uint(Ws[(cur * 16 + k + 4 + c) * WPAD + n]);
            }
#pragma unroll
            for (int mt = 0; mt < 4; ++mt)
#pragma unroll
                for (int nt = 0; nt < 4; ++nt)
                    mma_tf32(acc[mt][nt], aF[mt][0], aF[mt][1], aF[mt][2], aF[mt][3],
                             bF[nt][0], bF[nt][1]);
        }
        if (kc < 7) {
            const int nxt = cur ^ 1;
#pragma unroll
            for (int it = 0; it < 2; ++it) {
                int row = a_row0 + it * 64;
                float* d = &As[(nxt * 128 + row) * APAD + a_c4];
                d[0] = __uint_as_float(f2tf32(pa[it].x));
                d[1] = __uint_as_float(f2tf32(pa[it].y));
                d[2] = __uint_as_float(f2tf32(pa[it].z));
                d[3] = __uint_as_float(f2tf32(pa[it].w));
                int kk = w_k0 + it * 8;
                float* e = &Ws[(nxt * 16 + kk) * WPAD + w_c4];
                e[0] = __uint_as_float(f2tf32(pw[it].x));
                e[1] = __uint_as_float(f2tf32(pw[it].y));
                e[2] = __uint_as_float(f2tf32(pw[it].z));
                e[3] = __uint_as_float(f2tf32(pw[it].w));
            }
            __syncthreads();
        }
    }

    // epilogue 1: T = relu(acc + b1), tf32-rounded, into Ts; reset acc
#pragma unroll
    for (int nt = 0; nt < 4; ++nt) {
        const int col = warp_n * 32 + nt * 8 + (c << 1);
        const float bx = __ldg(b1 + col);
        const float by = __ldg(b1 + col + 1);
#pragma unroll
        for (int mt = 0; mt < 4; ++mt) {
            const int r0 = warp_m * 64 + mt * 16 + g;
            Ts[r0 * TPAD + col]     = __uint_as_float(f2tf32(fmaxf(acc[mt][nt][0] + bx, 0.0f)));
            Ts[r0 * TPAD + col + 1] = __uint_as_float(f2tf32(fmaxf(acc[mt][nt][1] + by, 0.0f)));
            Ts[(r0 + 8) * TPAD + col]     = __uint_as_float(f2tf32(fmaxf(acc[mt][nt][2] + bx, 0.0f)));
            Ts[(r0 + 8) * TPAD + col + 1] = __uint_as_float(f2tf32(fmaxf(acc[mt][nt][3] + by, 0.0f)));
#pragma unroll
            for (int q = 0; q < 4; ++q) acc[mt][nt][q] = 0.0f;
        }
    }
    __syncthreads();

    // ================= GEMM 2: C = relu(T @ W2 + b2) =================
    {
#pragma unroll
        for (int it = 0; it < 2; ++it) {
            int k = w_k0 + it * 8;
            float4 wv = __ldg((const float4*)(W2 + k * 128 + w_c4));
            float* e = &Ws[k * WPAD + w_c4];
            e[0] = __uint_as_float(f2tf32(wv.x));
            e[1] = __uint_as_float(f2tf32(wv.y));
            e[2] = __uint_as_float(f2tf32(wv.z));
            e[3] = __uint_as_float(f2tf32(wv.w));
        }
    }
    __syncthreads();

#pragma unroll 1
    for (int kc = 0; kc < 8; ++kc) {
        const int cur = kc & 1;
        float4 pw[2];
        if (kc < 7) {
#pragma unroll
            for (int it = 0; it < 2; ++it) {
                int k = w_k0 + it * 8;
                pw[it] = __ldg((const float4*)(W2 + ((kc + 1) * 16 + k) * 128 + w_c4));
            }
        }
#pragma unroll
        for (int ks = 0; ks < 2; ++ks) {
            const int k = kc * 16 + ks * 8;
            uint32_t aF[4][4], bF[4][2];
#pragma unroll
            for (int mt = 0; mt < 4; ++mt) {
                const int m = warp_m * 64 + mt * 16 + g;
                const float* p0 = &Ts[m * TPAD + k + c];
                const float* p1 = &Ts[(m + 8) * TPAD + k + c];
                aF[mt][0] = __float_as_uint(p0[0]);
                aF[mt][1] = __float_as_uint(p1[0]);
                aF[mt][2] = __float_as_uint(p0[4]);
                aF[mt][3] = __float_as_uint(p1[4]);
            }
#pragma unroll
            for (int nt = 0; nt < 4; ++nt) {
                const int n = warp_n * 32 + nt * 8 + g;
                bF[nt][0] = __float_as_uint(Ws[(cur * 16 + (ks * 8) + c) * WPAD + n]);
                bF[nt][1] = __float_as_uint(Ws[(cur * 16 + (ks * 8) + 4 + c) * WPAD + n]);
            }
#pragma unroll
            for (int mt = 0; mt < 4; ++mt)
#pragma unroll
                for (int nt = 0; nt < 4; ++nt)
                    mma_tf32(acc[mt][nt], aF[mt][0], aF[mt][1], aF[mt][2], aF[mt][3],
                             bF[nt][0], bF[nt][1]);
        }
        if (kc < 7) {
            const int nxt = cur ^ 1;
#pragma unroll
            for (int it = 0; it < 2; ++it) {
                int kk = w_k0 + it * 8;
                float* e = &Ws[(nxt * 16 + kk) * WPAD + w_c4];
                e[0] = __uint_as_float(f2tf32(pw[it].x));
                e[1] = __uint_as_float(f2tf32(pw[it].y));
                e[2] = __uint_as_float(f2tf32(pw[it].z));
                e[3] = __uint_as_float(f2tf32(pw[it].w));
            }
            __syncthreads();
        }
    }

    // epilogue 2
#pragma unroll
    for (int nt = 0; nt < 4; ++nt) {
        const int col = warp_n * 32 + nt * 8 + (c << 1);
        const float bx = __ldg(b2 + col);
        const float by = __ldg(b2 + col + 1);
#pragma unroll
        for (int mt = 0; mt < 4; ++mt) {
            const int row0 = rowBase + warp_m * 64 + mt * 16 + g;
            if (row0 < M) {
                float2 v;
                v.x = fmaxf(acc[mt][nt][0] + bx, 0.0f);
                v.y = fmaxf(acc[mt][nt][1] + by, 0.0f);
                *(float2*)(C + (long long)row0 * 128 + col) = v;
            }
            const int row1 = row0 + 8;
            if (row1 < M) {
                float2 v;
                v.x = fmaxf(acc[mt][nt][2] + bx, 0.0f);
                v.y = fmaxf(acc[mt][nt][3] + by, 0.0f);
                *(float2*)(C + (long long)row1 * 128 + col) = v;
            }
        }
    }
}

// ---------------------------------------------------------------------------
// out = log_softmax(H @ Wl + bl)
// ---------------------------------------------------------------------------
__global__ __launch_bounds__(256) void k_cls(int h_sel, const float* __restrict__ Wl,
                                             const float* __restrict__ bl,
                                             float* __restrict__ out, int M) {
    const float* H = bufsel(h_sel);
    __shared__ float sW[128 * 40];
    __shared__ float sb[40];
    __shared__ float srow[8][128];

    const int tid = threadIdx.x;
    for (int i = tid; i < 128 * 40; i += 256) sW[i] = Wl[i];
    if (tid < 40) sb[tid] = bl[tid];
    __syncthreads();

    const int warp = tid >> 5, lane = tid & 31;
    const long long r = (long long)blockIdx.x * 8 + warp;
    if (r >= M) return;

    ((float4*)srow[warp])[lane] = ((const float4*)(H + r * 128))[lane];
    __syncwarp();

    const int c0 = lane;
    const int c1 = lane + 32;
    float acc0 = sb[c0];
    float acc1 = (c1 < 40) ? sb[c1] : -1e30f;
#pragma unroll 4
    for (int f = 0; f < 128; ++f) {
        float hv = srow[warp][f];
        acc0 = fmaf(hv, sW[f * 40 + c0], acc0);
        if (c1 < 40) acc1 = fmaf(hv, sW[f * 40 + c1], acc1);
    }
    float mx = fmaxf(acc0, acc1);
#pragma unroll
    for (int o = 16; o; o >>= 1) mx = fmaxf(mx, __shfl_xor_sync(0xFFFFFFFFu, mx, o));
    float s = expf(acc0 - mx) + ((c1 < 40) ? expf(acc1 - mx) : 0.0f);
#pragma unroll
    for (int o = 16; o; o >>= 1) s += __shfl_xor_sync(0xFFFFFFFFu, s, o);
    float lse = mx + logf(s);
    out[r * 40 + c0] = acc0 - lse;
    if (c1 < 40) out[r * 40 + c1] = acc1 - lse;
}

// ---------------------------------------------------------------------------
extern "C" void kernel_launch(void* const* d_in, const int* in_sizes, int n_in,
                              void* d_out, int out_size) {
    const float* x   = (const float*)d_in[0];
    const void*  ei  = d_in[1];
    const float* ea  = (const float*)d_in[2];
    const float* eps1 = (const float*)d_in[3];
    const float* We1 = (const float*)d_in[4];
    const float* be1 = (const float*)d_in[5];
    const float* W11 = (const float*)d_in[6];
    const float* b11 = (const float*)d_in[7];
    const float* W12 = (const float*)d_in[8];
    const float* b12 = (const float*)d_in[9];
    const float* eps2 = (const float*)d_in[10];
    const float* We2 = (const float*)d_in[11];
    const float* be2 = (const float*)d_in[12];
    const float* W21 = (const float*)d_in[13];
    const float* b21 = (const float*)d_in[14];
    const float* W22 = (const float*)d_in[15];
    const float* b22 = (const float*)d_in[16];
    const float* Wl  = (const float*)d_in[17];
    const float* bl  = (const float*)d_in[18];
    float* out = (float*)d_out;

    const int N = in_sizes[0] / FDIM;
    const int E = in_sizes[2];

    const int gn = (N + 255) / 256;
    const int ge = (E + 255) / 256;
    const int nb = (N + 1023) / 1024;
    const int gz = (N + 7) / 8;
    const int gae = (E + 8 * ECHUNK - 1) / (8 * ECHUNK);
    const int gg = (N + 127) / 128;
    const int gc = (N + 7) / 8;

    const int mlp_smem = (2 * 128 * APAD + 2 * 16 * WPAD + 128 * TPAD) * 4;
    cudaFuncSetAttribute(k_mlp, cudaFuncAttributeMaxDynamicSharedMemorySize,
                         mlp_smem);

    // ---- CSR build (shared by both convs) ----
    k_detect<<<1, 32>>>((const long long*)ei, N);
    k_zero<<<gn, 256>>>(N);
    k_hist<<<ge, 256>>>(ei, E);
    k_scan1<<<nb, 1024>>>(N);
    k_scan2<<<1, 128>>>(nb);
    k_scan3<<<gn, 256>>>(N, E);
    k_scatter<<<ge, 256>>>(ei, ea, E);

    // ---- conv1: x (external) -> A -> B ----
    k_zero_h<<<gz, 256>>>((const float4*)x, -1, 0, eps1, N);
    k_aggr_edge<<<gae, 256>>>((const float4*)x, -1, 0, eps1,
                              (const float4*)We1, (const float4*)be1, E);
    k_mlp<<<gg, 256, mlp_smem>>>(0, W11, b11, W12, b12, 1, N);

    // ---- conv2: B -> A -> B ----
    k_zero_h<<<gz, 256>>>(nullptr, 1, 0, eps2, N);
    k_aggr_edge<<<gae, 256>>>(nullptr, 1, 0, eps2,
                              (const float4*)We2, (const float4*)be2, E);
    k_mlp<<<gg, 256, mlp_smem>>>(0, W21, b21, W22, b22, 1, N);

    // ---- classifier ----
    k_cls<<<gc, 256>>>(1, Wl, bl, out, N);
}

// round 9
// speedup vs baseline: 1.7632x; 1.7632x over previous
#include <cuda_runtime.h>
#include <cuda_fp16.h>
#include <cstdint>

// GINENet: 2x GINEConv(F=128) + classifier(40) + log_softmax
// N=100000, E=1600000, F=128.
//
// R9: revert R7/R8 edge-parallel experiment (aggregation is L2-BW-bound, not
// latency-bound; chunking regressed 496->870). Back to R6 per-node warps, but
// the per-edge gather now reads an fp16 shadow copy of the features (half the
// L2 bytes). Edge-linear term + base term + output stay fp32. tf32 fused MLP
// unchanged from R6.

#define NODES_MAX 100000
#define EDGE_MAX  1600000
#define FDIM 128

#define APAD 20
#define WPAD 136
#define TPAD 132

__device__ float  g_A[(size_t)NODES_MAX * FDIM];
__device__ float  g_B[(size_t)NODES_MAX * FDIM];
__device__ __half g_Xh[(size_t)NODES_MAX * FDIM];
__device__ int    g_rowptr[NODES_MAX + 1];
__device__ int    g_cur[NODES_MAX];
__device__ int    g_bsum[128];
__device__ int    g_srcS[EDGE_MAX];
__device__ float  g_eaS[EDGE_MAX];
__device__ int    g_is64;

__device__ __forceinline__ float* bufsel(int s) { return (s == 0) ? g_A : g_B; }

__device__ __forceinline__ uint32_t f2tf32(float f) {
    uint32_t r;
    asm("cvt.rna.tf32.f32 %0, %1;" : "=r"(r) : "f"(f));
    return r;
}

__device__ __forceinline__ void mma_tf32(float* c, uint32_t a0, uint32_t a1,
                                         uint32_t a2, uint32_t a3,
                                         uint32_t b0, uint32_t b1) {
    asm volatile(
        "mma.sync.aligned.m16n8k8.row.col.f32.tf32.tf32.f32 "
        "{%0,%1,%2,%3}, {%4,%5,%6,%7}, {%8,%9}, {%0,%1,%2,%3};"
        : "+f"(c[0]), "+f"(c[1]), "+f"(c[2]), "+f"(c[3])
        : "r"(a0), "r"(a1), "r"(a2), "r"(a3), "r"(b0), "r"(b1));
}

__device__ __forceinline__ float4 h4_to_f4(uint2 q) {
    __half2 lo = *reinterpret_cast<__half2*>(&q.x);
    __half2 hi = *reinterpret_cast<__half2*>(&q.y);
    float2 a = __half22float2(lo);
    float2 b = __half22float2(hi);
    return make_float4(a.x, a.y, b.x, b.y);
}

// ---------------------------------------------------------------------------
// Detect int64 vs int32 edge_index.
// ---------------------------------------------------------------------------
__global__ void k_detect(const long long* __restrict__ ei, int n_nodes) {
    if (threadIdx.x == 0 && blockIdx.x == 0) {
        int ok = 1;
        for (int i = 0; i < 64; ++i) {
            long long v = ei[i];
            if (v < 0 || v >= (long long)n_nodes) { ok = 0; break; }
        }
        g_is64 = ok;
    }
}

__device__ __forceinline__ long long load_idx(const void* ei, long long off) {
    if (g_is64) return __ldg((const long long*)ei + off);
    return (long long)__ldg((const int*)ei + off);
}

// ---------------------------------------------------------------------------
// CSR build: zero -> histogram(dst) -> 3-phase exclusive scan -> scatter
// ---------------------------------------------------------------------------
__global__ void k_zero(int n) {
    int i = blockIdx.x * blockDim.x + threadIdx.x;
    if (i < n) g_cur[i] = 0;
}

__global__ void k_hist(const void* __restrict__ ei, int E) {
    int e = blockIdx.x * blockDim.x + threadIdx.x;
    if (e >= E) return;
    int dst = (int)load_idx(ei, (long long)E + e);
    atomicAdd(&g_cur[dst], 1);
}

__global__ void k_scan1(int n) {
    const int tid = threadIdx.x, lane = tid & 31, warp = tid >> 5;
    const int idx = blockIdx.x * 1024 + tid;
    int v = (idx < n) ? g_cur[idx] : 0;
    int inc = v;
#pragma unroll
    for (int o = 1; o < 32; o <<= 1) {
        int t = __shfl_up_sync(0xFFFFFFFFu, inc, o);
        if (lane >= o) inc += t;
    }
    __shared__ int ws[32];
    if (lane == 31) ws[warp] = inc;
    __syncthreads();
    if (warp == 0) {
        int wv = ws[lane];
        int winc = wv;
#pragma unroll
        for (int o = 1; o < 32; o <<= 1) {
            int t = __shfl_up_sync(0xFFFFFFFFu, winc, o);
            if (lane >= o) winc += t;
        }
        ws[lane] = winc - wv;
    }
    __syncthreads();
    int excl = inc - v + ws[warp];
    if (idx <= n) g_rowptr[idx] = excl;
    if (tid == 1023) g_bsum[blockIdx.x] = excl + v;
}

__global__ void k_scan2(int nb) {
    __shared__ int s[128];
    int t = threadIdx.x;
    s[t] = (t < nb) ? g_bsum[t] : 0;
    __syncthreads();
    if (t == 0) {
        int run = 0;
        for (int i = 0; i < nb; ++i) { int v = s[i]; s[i] = run; run += v; }
    }
    __syncthreads();
    g_bsum[t] = s[t];
}

__global__ void k_scan3(int n, int E) {
    int idx = blockIdx.x * blockDim.x + threadIdx.x;
    if (idx < n) {
        int r = g_rowptr[idx] + g_bsum[idx >> 10];
        g_rowptr[idx] = r;
        g_cur[idx] = r;
    }
    if (idx == 0) g_rowptr[n] = E;
}

__global__ void k_scatter(const void* __restrict__ ei, const float* __restrict__ ea,
                          int E) {
    int e = blockIdx.x * blockDim.x + threadIdx.x;
    if (e >= E) return;
    int src = (int)load_idx(ei, e);
    int dst = (int)load_idx(ei, (long long)E + e);
    int pos = atomicAdd(&g_cur[dst], 1);
    g_srcS[pos] = src;
    g_eaS[pos] = __ldg(ea + e);
}

// ---------------------------------------------------------------------------
// fp16 shadow of the current feature matrix (gather payload halving).
// ---------------------------------------------------------------------------
__global__ void k_tohalf(const float4* __restrict__ in_ext, int in_sel, int n4) {
    int i = blockIdx.x * blockDim.x + threadIdx.x;
    if (i >= n4) return;
    const float4* in = in_ext ? in_ext : (const float4*)bufsel(in_sel);
    float4 v = __ldg(in + i);
    __half2 lo = __floats2half2_rn(v.x, v.y);
    __half2 hi = __floats2half2_rn(v.z, v.w);
    uint2 q;
    q.x = *reinterpret_cast<uint32_t*>(&lo);
    q.y = *reinterpret_cast<uint32_t*>(&hi);
    reinterpret_cast<uint2*>(g_Xh)[i] = q;
}

// ---------------------------------------------------------------------------
// Aggregation: one warp per node, lane owns 4 features. Gathers come from
// the fp16 shadow (256B/warp/edge); base term fp32.
//   h[v] = (1+eps)*x[v] + sum_e relu(xh[src_e] + a_e*We + be)
// ---------------------------------------------------------------------------
__global__ __launch_bounds__(256) void k_aggr(
    const float4* __restrict__ x_ext, int x_sel, int out_sel,
    const float* __restrict__ eps,
    const float4* __restrict__ We4, const float4* __restrict__ be4, int N) {
    const int tid = threadIdx.x;
    const int warp = tid >> 5, lane = tid & 31;
    const int v = blockIdx.x * 8 + warp;
    if (v >= N) return;

    const float4* x4 = x_ext ? x_ext : (const float4*)bufsel(x_sel);
    float4* h4 = (float4*)bufsel(out_sel);
    const uint2* xh = reinterpret_cast<const uint2*>(g_Xh);

    const float s = 1.0f + __ldg(eps);
    const float4 w = __ldg(We4 + lane);
    const float4 b = __ldg(be4 + lane);

    float4 acc = __ldg(x4 + (long long)v * 32 + lane);
    acc.x *= s; acc.y *= s; acc.z *= s; acc.w *= s;

    int e = g_rowptr[v];
    const int end = g_rowptr[v + 1];
#pragma unroll 1
    for (; e + 2 <= end; e += 2) {
        const int s0 = __ldg(g_srcS + e);
        const int s1 = __ldg(g_srcS + e + 1);
        const float a0 = __ldg(g_eaS + e);
        const float a1 = __ldg(g_eaS + e + 1);
        const float4 x0 = h4_to_f4(__ldg(xh + (long long)s0 * 32 + lane));
        const float4 x1 = h4_to_f4(__ldg(xh + (long long)s1 * 32 + lane));
        acc.x += fmaxf(fmaf(a0, w.x, b.x) + x0.x, 0.0f) +
                 fmaxf(fmaf(a1, w.x, b.x) + x1.x, 0.0f);
        acc.y += fmaxf(fmaf(a0, w.y, b.y) + x0.y, 0.0f) +
                 fmaxf(fmaf(a1, w.y, b.y) + x1.y, 0.0f);
        acc.z += fmaxf(fmaf(a0, w.z, b.z) + x0.z, 0.0f) +
                 fmaxf(fmaf(a1, w.z, b.z) + x1.z, 0.0f);
        acc.w += fmaxf(fmaf(a0, w.w, b.w) + x0.w, 0.0f) +
                 fmaxf(fmaf(a1, w.w, b.w) + x1.w, 0.0f);
    }
    if (e < end) {
        const int s0 = __ldg(g_srcS + e);
        const float a0 = __ldg(g_eaS + e);
        const float4 x0 = h4_to_f4(__ldg(xh + (long long)s0 * 32 + lane));
        acc.x += fmaxf(fmaf(a0, w.x, b.x) + x0.x, 0.0f);
        acc.y += fmaxf(fmaf(a0, w.y, b.y) + x0.y, 0.0f);
        acc.z += fmaxf(fmaf(a0, w.z, b.z) + x0.z, 0.0f);
        acc.w += fmaxf(fmaf(a0, w.w, b.w) + x0.w, 0.0f);
    }
    h4[(long long)v * 32 + lane] = acc;
}

// ---------------------------------------------------------------------------
// Fused MLP: C = relu( relu(A@W1 + b1) @ W2 + b2 )  (tf32 mma, unchanged R6)
// ---------------------------------------------------------------------------
__global__ __launch_bounds__(256, 2) void k_mlp(
    int a_sel, const float* __restrict__ W1, const float* __restrict__ b1,
    const float* __restrict__ W2, const float* __restrict__ b2,
    int c_sel, int M) {
    const float* A = bufsel(a_sel);
    float* C = bufsel(c_sel);

    extern __shared__ float smem[];
    float* As = smem;
    float* Ws = As + 2 * 128 * APAD;
    float* Ts = Ws + 2 * 16 * WPAD;

    const int tid = threadIdx.x;
    const int lane = tid & 31;
    const int wid = tid >> 5;
    const int warp_m = wid & 1;
    const int warp_n = wid >> 1;
    const int rowBase = blockIdx.x * 128;

    const int g = lane >> 2;
    const int c = lane & 3;

    float acc[4][4][4];
#pragma unroll
    for (int i = 0; i < 4; ++i)
#pragma unroll
        for (int j = 0; j < 4; ++j)
#pragma unroll
            for (int q = 0; q < 4; ++q) acc[i][j][q] = 0.0f;

    const int a_row0 = tid >> 2;
    const int a_c4 = (tid & 3) << 2;
    const int w_k0 = tid >> 5;
    const int w_c4 = (tid & 31) << 2;

    // ================= GEMM 1: T = relu(A @ W1 + b1) =================
    {
#pragma unroll
        for (int it = 0; it < 2; ++it) {
            int row = a_row0 + it * 64;
            int grow = rowBase + row;
            float4 v = make_float4(0.f, 0.f, 0.f, 0.f);
            if (grow < M) v = __ldg((const float4*)(A + (long long)grow * 128 + a_c4));
            float* d = &As[row * APAD + a_c4];
            d[0] = __uint_as_float(f2tf32(v.x));
            d[1] = __uint_as_float(f2tf32(v.y));
            d[2] = __uint_as_float(f2tf32(v.z));
            d[3] = __uint_as_float(f2tf32(v.w));
            int k = w_k0 + it * 8;
            float4 wv = __ldg((const float4*)(W1 + k * 128 + w_c4));
            float* e = &Ws[k * WPAD + w_c4];
            e[0] = __uint_as_float(f2tf32(wv.x));
            e[1] = __uint_as_float(f2tf32(wv.y));
            e[2] = __uint_as_float(f2tf32(wv.z));
            e[3] = __uint_as_float(f2tf32(wv.w));
        }
    }
    __syncthreads();

#pragma unroll 1
    for (int kc = 0; kc < 8; ++kc) {
        const int cur = kc & 1;
        float4 pa[2], pw[2];
        if (kc < 7) {
#pragma unroll
            for (int it = 0; it < 2; ++it) {
                int row = a_row0 + it * 64;
                int grow = rowBase + row;
                pa[it] = make_float4(0.f, 0.f, 0.f, 0.f);
                if (grow < M)
                    pa[it] = __ldg((const float4*)(A + (long long)grow * 128 +
                                                   (kc + 1) * 16 + a_c4));
                int k = w_k0 + it * 8;
                pw[it] = __ldg((const float4*)(W1 + ((kc + 1) * 16 + k) * 128 + w_c4));
            }
        }
#pragma unroll
        for (int ks = 0; ks < 2; ++ks) {
            const int k = ks * 8;
            uint32_t aF[4][4], bF[4][2];
#pragma unroll
            for (int mt = 0; mt < 4; ++mt) {
                const int m = warp_m * 64 + mt * 16 + g;
                const float* p0 = &As[(cur * 128 + m) * APAD + k + c];
                const float* p1 = &As[(cur * 128 + m + 8) * APAD + k + c];
                aF[mt][0] = __float_as_uint(p0[0]);
                aF[mt][1] = __float_as_uint(p1[0]);
                aF[mt][2] = __float_as_uint(p0[4]);
                aF[mt][3] = __float_as_uint(p1[4]);
            }
#pragma unroll
            for (int nt = 0; nt < 4; ++nt) {
                const int n = warp_n * 32 + nt * 8 + g;
                bF[nt][0] = __float_as_uint(Ws[(cur * 16 + k + c) * WPAD + n]);
                bF[nt][1] = __float_as_uint(Ws[(cur * 16 + k + 4 + c) * WPAD + n]);
            }
#pragma unroll
            for (int mt = 0; mt < 4; ++mt)
#pragma unroll
                for (int nt = 0; nt < 4; ++nt)
                    mma_tf32(acc[mt][nt], aF[mt][0], aF[mt][1], aF[mt][2], aF[mt][3],
                             bF[nt][0], bF[nt][1]);
        }
        if (kc < 7) {
            const int nxt = cur ^ 1;
#pragma unroll
            for (int it = 0; it < 2; ++it) {
                int row = a_row0 + it * 64;
                float* d = &As[(nxt * 128 + row) * APAD + a_c4];
                d[0] = __uint_as_float(f2tf32(pa[it].x));
                d[1] = __uint_as_float(f2tf32(pa[it].y));
                d[2] = __uint_as_float(f2tf32(pa[it].z));
                d[3] = __uint_as_float(f2tf32(pa[it].w));
                int kk = w_k0 + it * 8;
                float* e = &Ws[(nxt * 16 + kk) * WPAD + w_c4];
                e[0] = __uint_as_float(f2tf32(pw[it].x));
                e[1] = __uint_as_float(f2tf32(pw[it].y));
                e[2] = __uint_as_float(f2tf32(pw[it].z));
                e[3] = __uint_as_float(f2tf32(pw[it].w));
            }
            __syncthreads();
        }
    }

    // epilogue 1: T = relu(acc + b1), tf32-rounded, into Ts; reset acc
#pragma unroll
    for (int nt = 0; nt < 4; ++nt) {
        const int col = warp_n * 32 + nt * 8 + (c << 1);
        const float bx = __ldg(b1 + col);
        const float by = __ldg(b1 + col + 1);
#pragma unroll
        for (int mt = 0; mt < 4; ++mt) {
            const int r0 = warp_m * 64 + mt * 16 + g;
            Ts[r0 * TPAD + col]     = __uint_as_float(f2tf32(fmaxf(acc[mt][nt][0] + bx, 0.0f)));
            Ts[r0 * TPAD + col + 1] = __uint_as_float(f2tf32(fmaxf(acc[mt][nt][1] + by, 0.0f)));
            Ts[(r0 + 8) * TPAD + col]     = __uint_as_float(f2tf32(fmaxf(acc[mt][nt][2] + bx, 0.0f)));
            Ts[(r0 + 8) * TPAD + col + 1] = __uint_as_float(f2tf32(fmaxf(acc[mt][nt][3] + by, 0.0f)));
#pragma unroll
            for (int q = 0; q < 4; ++q) acc[mt][nt][q] = 0.0f;
        }
    }
    __syncthreads();

    // ================= GEMM 2: C = relu(T @ W2 + b2) =================
    {
#pragma unroll
        for (int it = 0; it < 2; ++it) {
            int k = w_k0 + it * 8;
            float4 wv = __ldg((const float4*)(W2 + k * 128 + w_c4));
            float* e = &Ws[k * WPAD + w_c4];
            e[0] = __uint_as_float(f2tf32(wv.x));
            e[1] = __uint_as_float(f2tf32(wv.y));
            e[2] = __uint_as_float(f2tf32(wv.z));
            e[3] = __uint_as_float(f2tf32(wv.w));
        }
    }
    __syncthreads();

#pragma unroll 1
    for (int kc = 0; kc < 8; ++kc) {
        const int cur = kc & 1;
        float4 pw[2];
        if (kc < 7) {
#pragma unroll
            for (int it = 0; it < 2; ++it) {
                int k = w_k0 + it * 8;
                pw[it] = __ldg((const float4*)(W2 + ((kc + 1) * 16 + k) * 128 + w_c4));
            }
        }
#pragma unroll
        for (int ks = 0; ks < 2; ++ks) {
            const int k = kc * 16 + ks * 8;
            uint32_t aF[4][4], bF[4][2];
#pragma unroll
            for (int mt = 0; mt < 4; ++mt) {
                const int m = warp_m * 64 + mt * 16 + g;
                const float* p0 = &Ts[m * TPAD + k + c];
                const float* p1 = &Ts[(m + 8) * TPAD + k + c];
                aF[mt][0] = __float_as_uint(p0[0]);
                aF[mt][1] = __float_as_uint(p1[0]);
                aF[mt][2] = __float_as_uint(p0[4]);
                aF[mt][3] = __float_as_uint(p1[4]);
            }
#pragma unroll
            for (int nt = 0; nt < 4; ++nt) {
                const int n = warp_n * 32 + nt * 8 + g;
                bF[nt][0] = __float_as_uint(Ws[(cur * 16 + (ks * 8) + c) * WPAD + n]);
                bF[nt][1] = __float_as_uint(Ws[(cur * 16 + (ks * 8) + 4 + c) * WPAD + n]);
            }
#pragma unroll
            for (int mt = 0; mt < 4; ++mt)
#pragma unroll
                for (int nt = 0; nt < 4; ++nt)
                    mma_tf32(acc[mt][nt], aF[mt][0], aF[mt][1], aF[mt][2], aF[mt][3],
                             bF[nt][0], bF[nt][1]);
        }
        if (kc < 7) {
            const int nxt = cur ^ 1;
#pragma unroll
            for (int it = 0; it < 2; ++it) {
                int kk = w_k0 + it * 8;
                float* e = &Ws[(nxt * 16 + kk) * WPAD + w_c4];
                e[0] = __uint_as_float(f2tf32(pw[it].x));
                e[1] = __uint_as_float(f2tf32(pw[it].y));
                e[2] = __uint_as_float(f2tf32(pw[it].z));
                e[3] = __uint_as_float(f2tf32(pw[it].w));
            }
            __syncthreads();
        }
    }

    // epilogue 2
#pragma unroll
    for (int nt = 0; nt < 4; ++nt) {
        const int col = warp_n * 32 + nt * 8 + (c << 1);
        const float bx = __ldg(b2 + col);
        const float by = __ldg(b2 + col + 1);
#pragma unroll
        for (int mt = 0; mt < 4; ++mt) {
            const int row0 = rowBase + warp_m * 64 + mt * 16 + g;
            if (row0 < M) {
                float2 v;
                v.x = fmaxf(acc[mt][nt][0] + bx, 0.0f);
                v.y = fmaxf(acc[mt][nt][1] + by, 0.0f);
                *(float2*)(C + (long long)row0 * 128 + col) = v;
            }
            const int row1 = row0 + 8;
            if (row1 < M) {
                float2 v;
                v.x = fmaxf(acc[mt][nt][2] + bx, 0.0f);
                v.y = fmaxf(acc[mt][nt][3] + by, 0.0f);
                *(float2*)(C + (long long)row1 * 128 + col) = v;
            }
        }
    }
}

// ---------------------------------------------------------------------------
// out = log_softmax(H @ Wl + bl)
// ---------------------------------------------------------------------------
__global__ __launch_bounds__(256) void k_cls(int h_sel, const float* __restrict__ Wl,
                                             const float* __restrict__ bl,
                                             float* __restrict__ out, int M) {
    const float* H = bufsel(h_sel);
    __shared__ float sW[128 * 40];
    __shared__ float sb[40];
    __shared__ float srow[8][128];

    const int tid = threadIdx.x;
    for (int i = tid; i < 128 * 40; i += 256) sW[i] = Wl[i];
    if (tid < 40) sb[tid] = bl[tid];
    __syncthreads();

    const int warp = tid >> 5, lane = tid & 31;
    const long long r = (long long)blockIdx.x * 8 + warp;
    if (r >= M) return;

    ((float4*)srow[warp])[lane] = ((const float4*)(H + r * 128))[lane];
    __syncwarp();

    const int c0 = lane;
    const int c1 = lane + 32;
    float acc0 = sb[c0];
    float acc1 = (c1 < 40) ? sb[c1] : -1e30f;
#pragma unroll 4
    for (int f = 0; f < 128; ++f) {
        float hv = srow[warp][f];
        acc0 = fmaf(hv, sW[f * 40 + c0], acc0);
        if (c1 < 40) acc1 = fmaf(hv, sW[f * 40 + c1], acc1);
    }
    float mx = fmaxf(acc0, acc1);
#pragma unroll
    for (int o = 16; o; o >>= 1) mx = fmaxf(mx, __shfl_xor_sync(0xFFFFFFFFu, mx, o));
    float s = expf(acc0 - mx) + ((c1 < 40) ? expf(acc1 - mx) : 0.0f);
#pragma unroll
    for (int o = 16; o; o >>= 1) s += __shfl_xor_sync(0xFFFFFFFFu, s, o);
    float lse = mx + logf(s);
    out[r * 40 + c0] = acc0 - lse;
    if (c1 < 40) out[r * 40 + c1] = acc1 - lse;
}

// ---------------------------------------------------------------------------
extern "C" void kernel_launch(void* const* d_in, const int* in_sizes, int n_in,
                              void* d_out, int out_size) {
    const float* x   = (const float*)d_in[0];
    const void*  ei  = d_in[1];
    const float* ea  = (const float*)d_in[2];
    const float* eps1 = (const float*)d_in[3];
    const float* We1 = (const float*)d_in[4];
    const float* be1 = (const float*)d_in[5];
    const float* W11 = (const float*)d_in[6];
    const float* b11 = (const float*)d_in[7];
    const float* W12 = (const float*)d_in[8];
    const float* b12 = (const float*)d_in[9];
    const float* eps2 = (const float*)d_in[10];
    const float* We2 = (const float*)d_in[11];
    const float* be2 = (const float*)d_in[12];
    const float* W21 = (const float*)d_in[13];
    const float* b21 = (const float*)d_in[14];
    const float* W22 = (const float*)d_in[15];
    const float* b22 = (const float*)d_in[16];
    const float* Wl  = (const float*)d_in[17];
    const float* bl  = (const float*)d_in[18];
    float* out = (float*)d_out;

    const int N = in_sizes[0] / FDIM;
    const int E = in_sizes[2];

    const int gn = (N + 255) / 256;
    const int ge = (E + 255) / 256;
    const int nb = (N + 1023) / 1024;
    const int n4 = N * (FDIM / 4);
    const int gh = (n4 + 255) / 256;
    const int ga = (N + 7) / 8;
    const int gg = (N + 127) / 128;
    const int gc = (N + 7) / 8;

    const int mlp_smem = (2 * 128 * APAD + 2 * 16 * WPAD + 128 * TPAD) * 4;
    cudaFuncSetAttribute(k_mlp, cudaFuncAttributeMaxDynamicSharedMemorySize,
                         mlp_smem);

    // ---- CSR build (shared by both convs) ----
    k_detect<<<1, 32>>>((const long long*)ei, N);
    k_zero<<<gn, 256>>>(N);
    k_hist<<<ge, 256>>>(ei, E);
    k_scan1<<<nb, 1024>>>(N);
    k_scan2<<<1, 128>>>(nb);
    k_scan3<<<gn, 256>>>(N, E);
    k_scatter<<<ge, 256>>>(ei, ea, E);

    // ---- conv1: x (external) -> A -> B ----
    k_tohalf<<<gh, 256>>>((const float4*)x, -1, n4);
    k_aggr<<<ga, 256>>>((const float4*)x, -1, 0, eps1,
                        (const float4*)We1, (const float4*)be1, N);
    k_mlp<<<gg, 256, mlp_smem>>>(0, W11, b11, W12, b12, 1, N);

    // ---- conv2: B -> A -> B ----
    k_tohalf<<<gh, 256>>>(nullptr, 1, n4);
    k_aggr<<<ga, 256>>>(nullptr, 1, 0, eps2,
                        (const float4*)We2, (const float4*)be2, N);
    k_mlp<<<gg, 256, mlp_smem>>>(0, W21, b21, W22, b22, 1, N);

    // ---- classifier ----
    k_cls<<<gc, 256>>>(1, Wl, bl, out, N);
}